// round 1
// baseline (speedup 1.0000x reference)
#include <cuda_runtime.h>
#include <stdint.h>

// Problem dims (fixed by reference):
//   S=4096 samples, M=32 slots, D=420, H=840
//   L1: Y1[131072,420] = relu(X @ W1^T + b1)
//   L2: Y2[131072,420] = relu(Y1 @ W2^T + b2)
//   pool: pooled[4096,420] = masked mean over first numInputs[s] of 32 slots
//   L3: Y3[4096,840] = relu(pooled @ W3^T + b3)
//   L4: out[4096,420] = relu(Y3 @ W4^T + b4)

#define S_SAMP 4096
#define M_SLOT 32
#define D_FEAT 420
#define H_FEAT 840
#define ROWS_L12 (S_SAMP * M_SLOT)   // 131072

// Scratch (allocation-free rule: __device__ globals)
__device__ float g_Y1[(size_t)ROWS_L12 * D_FEAT];    // 220 MB
__device__ float g_Y2[(size_t)ROWS_L12 * D_FEAT];    // 220 MB
__device__ float g_pooled[(size_t)S_SAMP * D_FEAT];  // 6.9 MB
__device__ float g_Y3[(size_t)S_SAMP * H_FEAT];      // 13.8 MB

// ---------------------------------------------------------------------------
// Tiled fp32 GEMM with fused bias + relu.
//   C[r, c] = relu( sum_k A[r,k] * W[c,k] + bias[c] )
// A: [Mrows, K] row-major, W: [N, K] row-major (i.e. we compute A @ W^T).
// BM=128, BN=64, BK=16; 128 threads; 8x8 register tile per thread.
// Mrows must be a multiple of 128 (true for all calls). N, K arbitrary.
// ---------------------------------------------------------------------------
#define BM 128
#define BN 64
#define BK 16
#define TM 8
#define TN 8

__global__ __launch_bounds__(128) void gemm_bias_relu(
    const float* __restrict__ A, const float* __restrict__ W,
    const float* __restrict__ bias, float* __restrict__ C,
    int Mrows, int N, int K)
{
    __shared__ float As[BK][BM];
    __shared__ float Ws[BK][BN];

    const int tid = threadIdx.x;       // 0..127
    const int cg  = tid & 7;           // col group 0..7  -> cols cg*8..cg*8+7
    const int rg  = tid >> 3;          // row group 0..15 -> rows rg*8..rg*8+7
    const int row0 = blockIdx.y * BM;  // always fully in-range
    const int col0 = blockIdx.x * BN;

    float acc[TM][TN];
    #pragma unroll
    for (int i = 0; i < TM; i++)
        #pragma unroll
        for (int j = 0; j < TN; j++) acc[i][j] = 0.f;

    for (int k0 = 0; k0 < K; k0 += BK) {
        // --- load A tile: thread t loads row (row0+t), k0..k0+BK-1 ---
        {
            const float* a = A + (size_t)(row0 + tid) * K;
            #pragma unroll
            for (int j = 0; j < BK; j++) {
                int k = k0 + j;
                As[j][tid] = (k < K) ? a[k] : 0.f;
            }
        }
        // --- load W tile: thread t handles n = col0 + t/2, k-half = (t&1)*8 ---
        {
            int nl = tid >> 1;
            int n  = col0 + nl;
            int kh = (tid & 1) * 8;
            const float* w = W + (size_t)n * K;
            bool nok = (n < N);
            #pragma unroll
            for (int j = 0; j < 8; j++) {
                int k = k0 + kh + j;
                Ws[kh + j][nl] = (nok && k < K) ? w[k] : 0.f;
            }
        }
        __syncthreads();

        #pragma unroll
        for (int kk = 0; kk < BK; kk++) {
            float af[TM], wf[TN];
            #pragma unroll
            for (int i = 0; i < TM; i++) af[i] = As[kk][rg * TM + i];
            #pragma unroll
            for (int j = 0; j < TN; j++) wf[j] = Ws[kk][cg * TN + j];
            #pragma unroll
            for (int i = 0; i < TM; i++)
                #pragma unroll
                for (int j = 0; j < TN; j++)
                    acc[i][j] = fmaf(af[i], wf[j], acc[i][j]);
        }
        __syncthreads();
    }

    // --- epilogue: bias + relu, masked on N ---
    #pragma unroll
    for (int i = 0; i < TM; i++) {
        int r = row0 + rg * TM + i;
        float* crow = C + (size_t)r * N;
        #pragma unroll
        for (int j = 0; j < TN; j++) {
            int c = col0 + cg * TN + j;
            if (c < N) {
                float v = acc[i][j] + bias[c];
                crow[c] = fmaxf(v, 0.f);
            }
        }
    }
}

// ---------------------------------------------------------------------------
// Ragged mean pool: pooled[s, d] = (1/n_s) * sum_{m < n_s} Y2[s, m, d]
// One CTA per sample; threads stride over d (coalesced per m-row).
// ---------------------------------------------------------------------------
__global__ __launch_bounds__(256) void pool_kernel(
    const float* __restrict__ Y2, const int* __restrict__ numInputs,
    float* __restrict__ pooled)
{
    int s = blockIdx.x;
    int n = numInputs[s];
    float inv = 1.0f / (float)n;
    const float* base = Y2 + (size_t)s * M_SLOT * D_FEAT;
    for (int d = threadIdx.x; d < D_FEAT; d += blockDim.x) {
        float sum = 0.f;
        for (int m = 0; m < n; m++) sum += base[(size_t)m * D_FEAT + d];
        pooled[(size_t)s * D_FEAT + d] = sum * inv;
    }
}

// ---------------------------------------------------------------------------
extern "C" void kernel_launch(void* const* d_in, const int* in_sizes, int n_in,
                              void* d_out, int out_size)
{
    (void)in_sizes; (void)n_in; (void)out_size;
    const float* all_x     = (const float*)d_in[0];   // [4096,32,420]
    const int*   numInputs = (const int*)  d_in[1];   // [4096]
    const float* W1 = (const float*)d_in[2];          // [420,420]
    const float* b1 = (const float*)d_in[3];
    const float* W2 = (const float*)d_in[4];          // [420,420]
    const float* b2 = (const float*)d_in[5];
    const float* W3 = (const float*)d_in[6];          // [840,420]
    const float* b3 = (const float*)d_in[7];
    const float* W4 = (const float*)d_in[8];          // [420,840]
    const float* b4 = (const float*)d_in[9];
    float* out = (float*)d_out;                       // [4096,1,420]

    float* Y1 = nullptr; float* Y2 = nullptr; float* P = nullptr; float* Y3 = nullptr;
    cudaGetSymbolAddress((void**)&Y1, g_Y1);
    cudaGetSymbolAddress((void**)&Y2, g_Y2);
    cudaGetSymbolAddress((void**)&P,  g_pooled);
    cudaGetSymbolAddress((void**)&Y3, g_Y3);

    dim3 blk(128);

    // L1: [131072,420] x [420,420]^T
    {
        dim3 grid((D_FEAT + BN - 1) / BN, ROWS_L12 / BM);   // (7, 1024)
        gemm_bias_relu<<<grid, blk>>>(all_x, W1, b1, Y1, ROWS_L12, D_FEAT, D_FEAT);
    }
    // L2
    {
        dim3 grid((D_FEAT + BN - 1) / BN, ROWS_L12 / BM);
        gemm_bias_relu<<<grid, blk>>>(Y1, W2, b2, Y2, ROWS_L12, D_FEAT, D_FEAT);
    }
    // Pool
    pool_kernel<<<S_SAMP, 256>>>(Y2, numInputs, P);
    // L3: [4096,420] x [840,420]^T -> [4096,840]
    {
        dim3 grid((H_FEAT + BN - 1) / BN, S_SAMP / BM);     // (14, 32)
        gemm_bias_relu<<<grid, blk>>>(P, W3, b3, Y3, S_SAMP, H_FEAT, D_FEAT);
    }
    // L4: [4096,840] x [420,840]^T -> out [4096,420]
    {
        dim3 grid((D_FEAT + BN - 1) / BN, S_SAMP / BM);     // (7, 32)
        gemm_bias_relu<<<grid, blk>>>(Y3, W4, b4, out, S_SAMP, D_FEAT, H_FEAT);
    }
}

// round 3
// speedup vs baseline: 2.5398x; 2.5398x over previous
#include <cuda_runtime.h>
#include <cuda_bf16.h>
#include <stdint.h>

// Dims: S=4096, M=32, D=420, H=840
#define S_SAMP 4096
#define M_SLOT 32
#define D_FEAT 420
#define H_FEAT 840
#define ROWS_L12 (S_SAMP * M_SLOT)   // 131072

// Scratch (__device__ globals: allocation-free rule)
__device__ float g_Y1[(size_t)ROWS_L12 * D_FEAT];
__device__ float g_Y2[(size_t)ROWS_L12 * D_FEAT];
__device__ float g_pooled[(size_t)S_SAMP * D_FEAT];
__device__ float g_Y3[(size_t)S_SAMP * H_FEAT];

// ---------------------------------------------------------------------------
// GEMM via mma.sync (HMMA, no arch-suffix needed) with bf16x3 emulation of
// fp32: A = Ah + Al, B = Bh + Bl; C += AhBh + AhBl + AlBh (AlBl ~2^-16, dropped)
//
// CTA tile 128(M) x 128(N), K chunks of 16. 256 threads = 8 warps in 4(m)x2(n).
// Warp tile 32x64 -> 2 m-frags x 8 n-blocks of m16n8k16.
// ---------------------------------------------------------------------------
#define BM 128
#define BN 128
#define BKC 16
#define ROWB 48                 // smem bytes per row (16 bf16 = 32B data + 16B pad)
#define ST_AH 0
#define ST_AL (128 * ROWB)      // 6144
#define ST_BH (2 * 128 * ROWB)  // 12288
#define ST_BL (3 * 128 * ROWB)  // 18432
#define STAGE (4 * 128 * ROWB)  // 24576
#define SMEM_TOTAL (2 * STAGE)  // 49152

__device__ __forceinline__ uint32_t smem_to_u32(const void* p) {
    uint32_t a;
    asm("{ .reg .u64 t; cvta.to.shared.u64 t, %1; cvt.u32.u64 %0, t; }" : "=r"(a) : "l"(p));
    return a;
}

#define LDSM_X4(R, addr) \
    asm volatile("ldmatrix.sync.aligned.m8n8.x4.shared.b16 {%0,%1,%2,%3}, [%4];" \
        : "=r"((R)[0]), "=r"((R)[1]), "=r"((R)[2]), "=r"((R)[3]) : "r"(addr))

#define MMA16816(C, A, B0, B1) \
    asm volatile("mma.sync.aligned.m16n8k16.row.col.f32.bf16.bf16.f32 " \
        "{%0,%1,%2,%3}, {%4,%5,%6,%7}, {%8,%9}, {%0,%1,%2,%3};" \
        : "+f"((C)[0]), "+f"((C)[1]), "+f"((C)[2]), "+f"((C)[3]) \
        : "r"((A)[0]), "r"((A)[1]), "r"((A)[2]), "r"((A)[3]), "r"(B0), "r"(B1))

__device__ __forceinline__ uint32_t pack2_hi(float x0, float x1, float& l0, float& l1) {
    __nv_bfloat16 h0 = __float2bfloat16(x0);
    __nv_bfloat16 h1 = __float2bfloat16(x1);
    l0 = x0 - __bfloat162float(h0);
    l1 = x1 - __bfloat162float(h1);
    return ((uint32_t)__bfloat16_as_ushort(h1) << 16) | __bfloat16_as_ushort(h0);
}
__device__ __forceinline__ uint32_t pack2(float x0, float x1) {
    return ((uint32_t)__bfloat16_as_ushort(__float2bfloat16(x1)) << 16) |
           __bfloat16_as_ushort(__float2bfloat16(x0));
}

// load 8 consecutive k-floats of one row, guarded + zero-padded
__device__ __forceinline__ void ldrow8(const float* __restrict__ src, int k, int K,
                                       bool ok, float* v) {
    if (ok && (k + 8 <= K)) {
        float4 u0 = *(const float4*)(src + k);
        float4 u1 = *(const float4*)(src + k + 4);
        v[0] = u0.x; v[1] = u0.y; v[2] = u0.z; v[3] = u0.w;
        v[4] = u1.x; v[5] = u1.y; v[6] = u1.z; v[7] = u1.w;
    } else {
        #pragma unroll
        for (int j = 0; j < 8; j++) v[j] = (ok && (k + j) < K) ? src[k + j] : 0.f;
    }
}

// convert 8 floats -> hi/lo bf16x2 and store 16B each into stage smem
__device__ __forceinline__ void stconv(char* smem, uint32_t stoff, uint32_t tile_off,
                                       int lr, int lh, const float* v) {
    uint32_t hi[4], lo[4];
    #pragma unroll
    for (int j = 0; j < 4; j++) {
        float l0, l1;
        hi[j] = pack2_hi(v[2 * j], v[2 * j + 1], l0, l1);
        lo[j] = pack2(l0, l1);
    }
    uint32_t base = stoff + tile_off + (uint32_t)lr * ROWB + (uint32_t)lh * 16;
    *(uint4*)(smem + base) = make_uint4(hi[0], hi[1], hi[2], hi[3]);
    *(uint4*)(smem + base + (ST_AL - ST_AH)) = make_uint4(lo[0], lo[1], lo[2], lo[3]);
}

__global__ __launch_bounds__(256) void gemm_mma(
    const float* __restrict__ A, const float* __restrict__ W,
    const float* __restrict__ bias, float* __restrict__ C,
    int Ntot, int K)
{
    extern __shared__ char smem[];
    const uint32_t sb = smem_to_u32(smem);
    const int tid = threadIdx.x;
    const int l = tid & 31;
    const int w = tid >> 5;
    const int wm = w & 3;          // 0..3 (32 rows each)
    const int wn = w >> 2;         // 0..1 (64 cols each)
    const int row0 = blockIdx.y * BM;
    const int noff = blockIdx.x * BN;

    // loader mapping: thread t -> row lr (0..127), k-half lh (0/1)
    const int lr = tid >> 1;
    const int lh = tid & 1;
    const float* aRow = A + (size_t)(row0 + lr) * K;
    const bool bok = (noff + lr) < Ntot;
    const float* bRow = W + (size_t)(noff + lr) * K;

    // ldmatrix lane addresses (within a tile)
    const uint32_t laneA = sb + (uint32_t)(((l & 7) + ((l >> 3) & 1) * 8) * ROWB
                         + (l >> 4) * 16 + wm * 32 * ROWB);
    const uint32_t laneB = sb + (uint32_t)(((l & 7) + (l >> 4) * 8) * ROWB
                         + ((l >> 3) & 1) * 16 + wn * 64 * ROWB);

    float acc[2][8][4];
    #pragma unroll
    for (int i = 0; i < 2; i++)
        #pragma unroll
        for (int j = 0; j < 8; j++)
            #pragma unroll
            for (int q = 0; q < 4; q++) acc[i][j][q] = 0.f;

    const int nch = (K + BKC - 1) / BKC;

    float pa[8], pb[8];
    ldrow8(aRow, lh * 8, K, true, pa);
    ldrow8(bRow, lh * 8, K, bok, pb);
    stconv(smem, 0, ST_AH, lr, lh, pa);
    stconv(smem, 0, ST_BH, lr, lh, pb);

    for (int c = 0; c < nch; c++) {
        if (c + 1 < nch) {
            int k0 = (c + 1) * BKC + lh * 8;
            ldrow8(aRow, k0, K, true, pa);
            ldrow8(bRow, k0, K, bok, pb);
        }
        __syncthreads();

        const uint32_t st = (uint32_t)(c & 1) * STAGE;
        uint32_t AH0[4], AH1[4], AL0[4], AL1[4], B[4][4];
        const uint32_t aH = laneA + st + ST_AH;
        const uint32_t aL = laneA + st + ST_AL;
        const uint32_t bH = laneB + st + ST_BH;
        const uint32_t bL = laneB + st + ST_BL;

        LDSM_X4(AH0, aH);
        LDSM_X4(AH1, aH + 16 * ROWB);
        LDSM_X4(AL0, aL);
        LDSM_X4(AL1, aL + 16 * ROWB);
        #pragma unroll
        for (int q = 0; q < 4; q++) LDSM_X4(B[q], bH + q * 16 * ROWB);

        // hh + lh products
        #pragma unroll
        for (int q = 0; q < 4; q++) {
            MMA16816(acc[0][2 * q],     AH0, B[q][0], B[q][1]);
            MMA16816(acc[1][2 * q],     AH1, B[q][0], B[q][1]);
            MMA16816(acc[0][2 * q + 1], AH0, B[q][2], B[q][3]);
            MMA16816(acc[1][2 * q + 1], AH1, B[q][2], B[q][3]);
            MMA16816(acc[0][2 * q],     AL0, B[q][0], B[q][1]);
            MMA16816(acc[1][2 * q],     AL1, B[q][0], B[q][1]);
            MMA16816(acc[0][2 * q + 1], AL0, B[q][2], B[q][3]);
            MMA16816(acc[1][2 * q + 1], AL1, B[q][2], B[q][3]);
        }
        // hl product (reload B regs with Bl)
        #pragma unroll
        for (int q = 0; q < 4; q++) LDSM_X4(B[q], bL + q * 16 * ROWB);
        #pragma unroll
        for (int q = 0; q < 4; q++) {
            MMA16816(acc[0][2 * q],     AH0, B[q][0], B[q][1]);
            MMA16816(acc[1][2 * q],     AH1, B[q][0], B[q][1]);
            MMA16816(acc[0][2 * q + 1], AH0, B[q][2], B[q][3]);
            MMA16816(acc[1][2 * q + 1], AH1, B[q][2], B[q][3]);
        }

        if (c + 1 < nch) {
            stconv(smem, (uint32_t)((c + 1) & 1) * STAGE, ST_AH, lr, lh, pa);
            stconv(smem, (uint32_t)((c + 1) & 1) * STAGE, ST_BH, lr, lh, pb);
        }
    }

    // ---- epilogue: bias + relu + store (float2 per 8-col block) ----
    const int r_base = row0 + wm * 32 + (l >> 2);
    const int c_base = noff + wn * 64 + (l & 3) * 2;
    float2 bs[8];
    #pragma unroll
    for (int nb = 0; nb < 8; nb++) {
        int cc = c_base + nb * 8;
        if (cc < Ntot) bs[nb] = make_float2(bias[cc], bias[cc + 1]);
        else           bs[nb] = make_float2(0.f, 0.f);
    }
    #pragma unroll
    for (int mf = 0; mf < 2; mf++) {
        #pragma unroll
        for (int nb = 0; nb < 8; nb++) {
            int cc = c_base + nb * 8;
            if (cc < Ntot) {
                int rr = r_base + mf * 16;
                float2 o0, o1;
                o0.x = fmaxf(acc[mf][nb][0] + bs[nb].x, 0.f);
                o0.y = fmaxf(acc[mf][nb][1] + bs[nb].y, 0.f);
                o1.x = fmaxf(acc[mf][nb][2] + bs[nb].x, 0.f);
                o1.y = fmaxf(acc[mf][nb][3] + bs[nb].y, 0.f);
                *(float2*)(C + (size_t)rr * Ntot + cc) = o0;
                *(float2*)(C + (size_t)(rr + 8) * Ntot + cc) = o1;
            }
        }
    }
}

// ---------------------------------------------------------------------------
// Ragged mean pool (float4): pooled[s,:] = mean(Y2[s, 0:n, :])
// ---------------------------------------------------------------------------
__global__ __launch_bounds__(128) void pool_kernel(
    const float* __restrict__ Y2, const int* __restrict__ numInputs,
    float* __restrict__ pooled)
{
    int s = blockIdx.x;
    int n = numInputs[s];
    float inv = 1.0f / (float)n;
    const float4* base = (const float4*)(Y2 + (size_t)s * M_SLOT * D_FEAT);
    float4* outp = (float4*)(pooled + (size_t)s * D_FEAT);
    for (int d4 = threadIdx.x; d4 < D_FEAT / 4; d4 += 128) {
        float4 acc = make_float4(0.f, 0.f, 0.f, 0.f);
        for (int m = 0; m < n; m++) {
            float4 v = base[(size_t)m * (D_FEAT / 4) + d4];
            acc.x += v.x; acc.y += v.y; acc.z += v.z; acc.w += v.w;
        }
        acc.x *= inv; acc.y *= inv; acc.z *= inv; acc.w *= inv;
        outp[d4] = acc;
    }
}

// ---------------------------------------------------------------------------
extern "C" void kernel_launch(void* const* d_in, const int* in_sizes, int n_in,
                              void* d_out, int out_size)
{
    (void)in_sizes; (void)n_in; (void)out_size;
    const float* all_x     = (const float*)d_in[0];
    const int*   numInputs = (const int*)  d_in[1];
    const float* W1 = (const float*)d_in[2];
    const float* b1 = (const float*)d_in[3];
    const float* W2 = (const float*)d_in[4];
    const float* b2 = (const float*)d_in[5];
    const float* W3 = (const float*)d_in[6];
    const float* b3 = (const float*)d_in[7];
    const float* W4 = (const float*)d_in[8];
    const float* b4 = (const float*)d_in[9];
    float* out = (float*)d_out;

    float *Y1, *Y2, *P, *Y3;
    cudaGetSymbolAddress((void**)&Y1, g_Y1);
    cudaGetSymbolAddress((void**)&Y2, g_Y2);
    cudaGetSymbolAddress((void**)&P,  g_pooled);
    cudaGetSymbolAddress((void**)&Y3, g_Y3);

    cudaFuncSetAttribute(gemm_mma, cudaFuncAttributeMaxDynamicSharedMemorySize, SMEM_TOTAL);

    // L1: [131072,420] = relu(X @ W1^T + b1), K=420, N=420 -> 4 n-tiles
    gemm_mma<<<dim3((D_FEAT + BN - 1) / BN, ROWS_L12 / BM), 256, SMEM_TOTAL>>>(
        all_x, W1, b1, Y1, D_FEAT, D_FEAT);
    // L2
    gemm_mma<<<dim3((D_FEAT + BN - 1) / BN, ROWS_L12 / BM), 256, SMEM_TOTAL>>>(
        Y1, W2, b2, Y2, D_FEAT, D_FEAT);
    // pool
    pool_kernel<<<S_SAMP, 128>>>(Y2, numInputs, P);
    // L3: [4096,840], K=420
    gemm_mma<<<dim3((H_FEAT + BN - 1) / BN, S_SAMP / BM), 256, SMEM_TOTAL>>>(
        P, W3, b3, Y3, H_FEAT, D_FEAT);
    // L4: [4096,420], K=840
    gemm_mma<<<dim3((D_FEAT + BN - 1) / BN, S_SAMP / BM), 256, SMEM_TOTAL>>>(
        Y3, W4, b4, out, D_FEAT, H_FEAT);
}

// round 5
// speedup vs baseline: 3.1802x; 1.2521x over previous
#include <cuda_runtime.h>
#include <cuda_bf16.h>
#include <stdint.h>

// Dims: S=4096, M=32, D=420, H=840
#define S_SAMP 4096
#define M_SLOT 32
#define D_FEAT 420
#define H_FEAT 840
#define ROWS_L12 (S_SAMP * M_SLOT)   // 131072
#define KP1 448                      // 420 padded to 32
#define KP2 896                      // 840 padded to 32

// ---------------- scratch planes (hi/lo bf16), zero-padded ------------------
__device__ __nv_bfloat16 g_Xh[(size_t)ROWS_L12 * KP1];
__device__ __nv_bfloat16 g_Xl[(size_t)ROWS_L12 * KP1];
__device__ __nv_bfloat16 g_Y1h[(size_t)ROWS_L12 * KP1];
__device__ __nv_bfloat16 g_Y1l[(size_t)ROWS_L12 * KP1];
__device__ __nv_bfloat16 g_Y2h[(size_t)ROWS_L12 * KP1];
__device__ __nv_bfloat16 g_Y2l[(size_t)ROWS_L12 * KP1];
__device__ __nv_bfloat16 g_Ph[(size_t)S_SAMP * KP1];
__device__ __nv_bfloat16 g_Pl[(size_t)S_SAMP * KP1];
__device__ __nv_bfloat16 g_Y3h[(size_t)S_SAMP * KP2];
__device__ __nv_bfloat16 g_Y3l[(size_t)S_SAMP * KP2];
__device__ __nv_bfloat16 g_W1h[512 * KP1], g_W1l[512 * KP1];
__device__ __nv_bfloat16 g_W2h[512 * KP1], g_W2l[512 * KP1];
__device__ __nv_bfloat16 g_W3h[896 * KP1], g_W3l[896 * KP1];
__device__ __nv_bfloat16 g_W4h[512 * KP2], g_W4l[512 * KP2];

// ---------------- asm helpers ----------------------------------------------
__device__ __forceinline__ uint32_t smem_to_u32(const void* p) {
    uint32_t a;
    asm("{ .reg .u64 t; cvta.to.shared.u64 t, %1; cvt.u32.u64 %0, t; }" : "=r"(a) : "l"(p));
    return a;
}
#define CP16(dst, src) \
    asm volatile("cp.async.cg.shared.global [%0], [%1], 16;" :: "r"(dst), "l"(src))
#define CP_COMMIT() asm volatile("cp.async.commit_group;" ::: "memory")
#define CP_WAIT(n)  asm volatile("cp.async.wait_group %0;" :: "n"(n) : "memory")

#define LDSM_X4(R, addr) \
    asm volatile("ldmatrix.sync.aligned.m8n8.x4.shared.b16 {%0,%1,%2,%3}, [%4];" \
        : "=r"((R)[0]), "=r"((R)[1]), "=r"((R)[2]), "=r"((R)[3]) : "r"(addr))

#define MMA16816(C, A, B0, B1) \
    asm volatile("mma.sync.aligned.m16n8k16.row.col.f32.bf16.bf16.f32 " \
        "{%0,%1,%2,%3}, {%4,%5,%6,%7}, {%8,%9}, {%0,%1,%2,%3};" \
        : "+f"((C)[0]), "+f"((C)[1]), "+f"((C)[2]), "+f"((C)[3]) \
        : "r"((A)[0]), "r"((A)[1]), "r"((A)[2]), "r"((A)[3]), "r"(B0), "r"(B1))

__device__ __forceinline__ void split2(float v, __nv_bfloat16& h, __nv_bfloat16& l) {
    h = __float2bfloat16(v);
    l = __float2bfloat16(v - __bfloat162float(h));
}

// ---------------- conversion kernels ---------------------------------------
// src [Rtot, K] fp32 -> (dh, dl) [Rp, Kp] bf16, zero-padded.
__global__ __launch_bounds__(128) void convert_split(
    const float* __restrict__ src, __nv_bfloat16* __restrict__ dh,
    __nv_bfloat16* __restrict__ dl, int Rtot, int K, int Kp)
{
    int r = blockIdx.x;
    bool rok = r < Rtot;
    const float* s = src + (size_t)r * K;
    size_t o = (size_t)r * Kp;
    for (int k = threadIdx.x; k < Kp; k += 128) {
        float v = (rok && k < K) ? s[k] : 0.f;
        __nv_bfloat16 h, l;
        split2(v, h, l);
        dh[o + k] = h; dl[o + k] = l;
    }
}

// ---------------- GEMM: planes in, planes or fp32 out -----------------------
// C[r,c] = relu( sum_k (Ah+Al)[r,k]*(Bh+Bl)[c,k] + bias[c] ), drop Al*Bl.
// CTA 128x128, BK=32, 2-stage cp.async pipeline, 8 warps (4m x 2n).
#define PL_SZ  (128 * 80)         // one plane per stage: 128 rows x 80B
#define PL_AH  0
#define PL_AL  (PL_SZ)
#define PL_BH  (2 * PL_SZ)
#define PL_BL  (3 * PL_SZ)
#define STAGE  (4 * PL_SZ)        // 40960
#define SMEM_TOTAL (2 * STAGE)    // 81920

__device__ __forceinline__ void issue_chunk(
    uint32_t sb, int stage, int c,
    const __nv_bfloat16* __restrict__ Ah, const __nv_bfloat16* __restrict__ Al,
    const __nv_bfloat16* __restrict__ Bh, const __nv_bfloat16* __restrict__ Bl,
    int row0, int noff, int Kp, int tid)
{
    uint32_t st = sb + (uint32_t)stage * STAGE;
    int k0 = c * 32;
    #pragma unroll
    for (int j = 0; j < 2; j++) {
        int i = tid + 256 * j;
        int row = i >> 2, c16 = i & 3;
        size_t offA = (size_t)(row0 + row) * Kp + k0 + c16 * 8;
        size_t offB = (size_t)(noff + row) * Kp + k0 + c16 * 8;
        uint32_t d = (uint32_t)(row * 80 + c16 * 16);
        CP16(st + PL_AH + d, Ah + offA);
        CP16(st + PL_AL + d, Al + offA);
        CP16(st + PL_BH + d, Bh + offB);
        CP16(st + PL_BL + d, Bl + offB);
    }
}

__global__ __launch_bounds__(256, 2) void gemm_mma(
    const __nv_bfloat16* __restrict__ Ah, const __nv_bfloat16* __restrict__ Al,
    const __nv_bfloat16* __restrict__ Bh, const __nv_bfloat16* __restrict__ Bl,
    const float* __restrict__ bias,
    float* __restrict__ Cf, __nv_bfloat16* __restrict__ Ch, __nv_bfloat16* __restrict__ Cl,
    int Ntot, int Kp, int KpOut, int mode)
{
    extern __shared__ char smem[];
    const uint32_t sb = smem_to_u32(smem);
    const int tid = threadIdx.x;
    const int l = tid & 31;
    const int w = tid >> 5;
    const int wm = w & 3;
    const int wn = w >> 2;
    const int row0 = blockIdx.y * 128;
    const int noff = blockIdx.x * 128;

    const uint32_t aoff = (uint32_t)(((l & 7) + ((l >> 3) & 1) * 8 + wm * 32) * 80 + (l >> 4) * 16);
    const uint32_t boff = (uint32_t)(((l & 7) + (l >> 4) * 8 + wn * 64) * 80 + ((l >> 3) & 1) * 16);

    float acc[2][8][4];
    #pragma unroll
    for (int i = 0; i < 2; i++)
        #pragma unroll
        for (int j = 0; j < 8; j++)
            #pragma unroll
            for (int q = 0; q < 4; q++) acc[i][j][q] = 0.f;

    const int nch = Kp >> 5;

    issue_chunk(sb, 0, 0, Ah, Al, Bh, Bl, row0, noff, Kp, tid);
    CP_COMMIT();

    for (int c = 0; c < nch; c++) {
        if (c + 1 < nch) {
            issue_chunk(sb, (c + 1) & 1, c + 1, Ah, Al, Bh, Bl, row0, noff, Kp, tid);
            CP_COMMIT();
            CP_WAIT(1);
        } else {
            CP_WAIT(0);
        }
        __syncthreads();

        const uint32_t stb = sb + (uint32_t)(c & 1) * STAGE;
        #pragma unroll
        for (int ks = 0; ks < 2; ks++) {
            const uint32_t col = ks * 32;
            uint32_t AH0[4], AH1[4], AL0[4], AL1[4], B[4][4];
            const uint32_t aH = stb + PL_AH + aoff + col;
            const uint32_t aL = stb + PL_AL + aoff + col;
            const uint32_t bH = stb + PL_BH + boff + col;
            const uint32_t bL = stb + PL_BL + boff + col;
            LDSM_X4(AH0, aH);
            LDSM_X4(AH1, aH + 16 * 80);
            LDSM_X4(AL0, aL);
            LDSM_X4(AL1, aL + 16 * 80);
            #pragma unroll
            for (int q = 0; q < 4; q++) LDSM_X4(B[q], bH + q * 16 * 80);
            #pragma unroll
            for (int q = 0; q < 4; q++) {
                MMA16816(acc[0][2 * q],     AH0, B[q][0], B[q][1]);
                MMA16816(acc[1][2 * q],     AH1, B[q][0], B[q][1]);
                MMA16816(acc[0][2 * q + 1], AH0, B[q][2], B[q][3]);
                MMA16816(acc[1][2 * q + 1], AH1, B[q][2], B[q][3]);
                MMA16816(acc[0][2 * q],     AL0, B[q][0], B[q][1]);
                MMA16816(acc[1][2 * q],     AL1, B[q][0], B[q][1]);
                MMA16816(acc[0][2 * q + 1], AL0, B[q][2], B[q][3]);
                MMA16816(acc[1][2 * q + 1], AL1, B[q][2], B[q][3]);
            }
            #pragma unroll
            for (int q = 0; q < 4; q++) LDSM_X4(B[q], bL + q * 16 * 80);
            #pragma unroll
            for (int q = 0; q < 4; q++) {
                MMA16816(acc[0][2 * q],     AH0, B[q][0], B[q][1]);
                MMA16816(acc[1][2 * q],     AH1, B[q][0], B[q][1]);
                MMA16816(acc[0][2 * q + 1], AH0, B[q][2], B[q][3]);
                MMA16816(acc[1][2 * q + 1], AH1, B[q][2], B[q][3]);
            }
        }
        __syncthreads();
    }

    // ---- epilogue ----
    const int r_base = row0 + wm * 32 + (l >> 2);
    const int c_base = noff + wn * 64 + (l & 3) * 2;
    float2 bs[8];
    #pragma unroll
    for (int nb = 0; nb < 8; nb++) {
        int cc = c_base + nb * 8;
        bs[nb] = (cc < Ntot) ? make_float2(bias[cc], bias[cc + 1]) : make_float2(0.f, 0.f);
    }
    #pragma unroll
    for (int mf = 0; mf < 2; mf++) {
        #pragma unroll
        for (int nb = 0; nb < 8; nb++) {
            int cc = c_base + nb * 8;
            int rr = r_base + mf * 16;
            bool valid = (cc < Ntot);
            float v00 = valid ? fmaxf(acc[mf][nb][0] + bs[nb].x, 0.f) : 0.f;
            float v01 = valid ? fmaxf(acc[mf][nb][1] + bs[nb].y, 0.f) : 0.f;
            float v10 = valid ? fmaxf(acc[mf][nb][2] + bs[nb].x, 0.f) : 0.f;
            float v11 = valid ? fmaxf(acc[mf][nb][3] + bs[nb].y, 0.f) : 0.f;
            if (mode == 0) {
                if (valid) {
                    *(float2*)(Cf + (size_t)rr * Ntot + cc) = make_float2(v00, v01);
                    *(float2*)(Cf + (size_t)(rr + 8) * Ntot + cc) = make_float2(v10, v11);
                }
            } else {
                if (cc < KpOut) {
                    __nv_bfloat16 h0, l0, h1, l1;
                    split2(v00, h0, l0); split2(v01, h1, l1);
                    __nv_bfloat162 hp, lp;
                    hp.x = h0; hp.y = h1; lp.x = l0; lp.y = l1;
                    *(__nv_bfloat162*)(Ch + (size_t)rr * KpOut + cc) = hp;
                    *(__nv_bfloat162*)(Cl + (size_t)rr * KpOut + cc) = lp;
                    split2(v10, h0, l0); split2(v11, h1, l1);
                    hp.x = h0; hp.y = h1; lp.x = l0; lp.y = l1;
                    *(__nv_bfloat162*)(Ch + (size_t)(rr + 8) * KpOut + cc) = hp;
                    *(__nv_bfloat162*)(Cl + (size_t)(rr + 8) * KpOut + cc) = lp;
                }
            }
        }
    }
}

// ---------------- ragged mean pool on planes --------------------------------
__global__ __launch_bounds__(128) void pool_kernel(
    const __nv_bfloat16* __restrict__ Y2h, const __nv_bfloat16* __restrict__ Y2l,
    const int* __restrict__ numInputs,
    __nv_bfloat16* __restrict__ Ph, __nv_bfloat16* __restrict__ Pl)
{
    int s = blockIdx.x;
    int n = numInputs[s];
    float inv = 1.0f / (float)n;
    size_t base = (size_t)s * M_SLOT * KP1;
    for (int d = threadIdx.x; d < KP1; d += 128) {
        float v = 0.f;
        if (d < D_FEAT) {
            float sum = 0.f;
            for (int m = 0; m < n; m++) {
                size_t o = base + (size_t)m * KP1 + d;
                sum += __bfloat162float(Y2h[o]) + __bfloat162float(Y2l[o]);
            }
            v = sum * inv;
        }
        __nv_bfloat16 h, l;
        split2(v, h, l);
        Ph[(size_t)s * KP1 + d] = h;
        Pl[(size_t)s * KP1 + d] = l;
    }
}

// ---------------------------------------------------------------------------
extern "C" void kernel_launch(void* const* d_in, const int* in_sizes, int n_in,
                              void* d_out, int out_size)
{
    (void)in_sizes; (void)n_in; (void)out_size;
    const float* all_x     = (const float*)d_in[0];
    const int*   numInputs = (const int*)  d_in[1];
    const float* W1 = (const float*)d_in[2];
    const float* b1 = (const float*)d_in[3];
    const float* W2 = (const float*)d_in[4];
    const float* b2 = (const float*)d_in[5];
    const float* W3 = (const float*)d_in[6];
    const float* b3 = (const float*)d_in[7];
    const float* W4 = (const float*)d_in[8];
    const float* b4 = (const float*)d_in[9];
    float* out = (float*)d_out;

    __nv_bfloat16 *Xh, *Xl, *Y1h, *Y1l, *Y2h, *Y2l, *Ph, *Pl, *Y3h, *Y3l;
    __nv_bfloat16 *W1h, *W1l, *W2h, *W2l, *W3h, *W3l, *W4h, *W4l;
    cudaGetSymbolAddress((void**)&Xh, g_Xh);   cudaGetSymbolAddress((void**)&Xl, g_Xl);
    cudaGetSymbolAddress((void**)&Y1h, g_Y1h); cudaGetSymbolAddress((void**)&Y1l, g_Y1l);
    cudaGetSymbolAddress((void**)&Y2h, g_Y2h); cudaGetSymbolAddress((void**)&Y2l, g_Y2l);
    cudaGetSymbolAddress((void**)&Ph, g_Ph);   cudaGetSymbolAddress((void**)&Pl, g_Pl);
    cudaGetSymbolAddress((void**)&Y3h, g_Y3h); cudaGetSymbolAddress((void**)&Y3l, g_Y3l);
    cudaGetSymbolAddress((void**)&W1h, g_W1h); cudaGetSymbolAddress((void**)&W1l, g_W1l);
    cudaGetSymbolAddress((void**)&W2h, g_W2h); cudaGetSymbolAddress((void**)&W2l, g_W2l);
    cudaGetSymbolAddress((void**)&W3h, g_W3h); cudaGetSymbolAddress((void**)&W3l, g_W3l);
    cudaGetSymbolAddress((void**)&W4h, g_W4h); cudaGetSymbolAddress((void**)&W4l, g_W4l);

    cudaFuncSetAttribute(gemm_mma, cudaFuncAttributeMaxDynamicSharedMemorySize, SMEM_TOTAL);

    // converts (bandwidth-trivial)
    convert_split<<<ROWS_L12, 128>>>(all_x, Xh, Xl, ROWS_L12, D_FEAT, KP1);
    convert_split<<<512, 128>>>(W1, W1h, W1l, D_FEAT, D_FEAT, KP1);
    convert_split<<<512, 128>>>(W2, W2h, W2l, D_FEAT, D_FEAT, KP1);
    convert_split<<<896, 128>>>(W3, W3h, W3l, H_FEAT, D_FEAT, KP1);
    convert_split<<<512, 128>>>(W4, W4h, W4l, D_FEAT, H_FEAT, KP2);

    // L1: planes out (KpOut=KP1)
    gemm_mma<<<dim3(4, ROWS_L12 / 128), 256, SMEM_TOTAL>>>(
        Xh, Xl, W1h, W1l, b1, nullptr, Y1h, Y1l, D_FEAT, KP1, KP1, 1);
    // L2
    gemm_mma<<<dim3(4, ROWS_L12 / 128), 256, SMEM_TOTAL>>>(
        Y1h, Y1l, W2h, W2l, b2, nullptr, Y2h, Y2l, D_FEAT, KP1, KP1, 1);
    // pool
    pool_kernel<<<S_SAMP, 128>>>(Y2h, Y2l, numInputs, Ph, Pl);
    // L3: N=840 -> 7 tiles, planes out (KpOut=KP2)
    gemm_mma<<<dim3(7, S_SAMP / 128), 256, SMEM_TOTAL>>>(
        Ph, Pl, W3h, W3l, b3, nullptr, Y3h, Y3l, H_FEAT, KP1, KP2, 1);
    // L4: K=896, fp32 out
    gemm_mma<<<dim3(4, S_SAMP / 128), 256, SMEM_TOTAL>>>(
        Y3h, Y3l, W4h, W4l, b4, out, nullptr, nullptr, D_FEAT, KP2, 0, 0);
}